// round 1
// baseline (speedup 1.0000x reference)
#include <cuda_runtime.h>
#include <math.h>

#define BB 16
#define TT 2048
#define EE 64
#define HS 16
#define KT 128   // keys per smem tile

// scratch: Q, K (post-RoPE) and V, [B*T, HS] row-major
__device__ float g_q[BB * TT * HS];
__device__ float g_k[BB * TT * HS];
__device__ float g_v[BB * TT * HS];

// ---------------------------------------------------------------------------
// Kernel 1: fused QKV projection + RoPE
// one thread per (b,t) row; weights staged in smem
// ---------------------------------------------------------------------------
__global__ __launch_bounds__(128) void qkv_rope_kernel(
    const float* __restrict__ x,
    const float* __restrict__ wq,
    const float* __restrict__ wk,
    const float* __restrict__ wv)
{
    __shared__ float swq[EE * HS];
    __shared__ float swk[EE * HS];
    __shared__ float swv[EE * HS];

    int tid = threadIdx.x;
    for (int i = tid; i < EE * HS; i += 128) {
        swq[i] = wq[i];
        swk[i] = wk[i];
        swv[i] = wv[i];
    }
    __syncthreads();

    int row = blockIdx.x * 128 + tid;       // 0 .. B*T-1
    int t = row & (TT - 1);

    const float4* xr = reinterpret_cast<const float4*>(x + (size_t)row * EE);

    float q[HS], k[HS], v[HS];
#pragma unroll
    for (int h = 0; h < HS; h++) { q[h] = 0.f; k[h] = 0.f; v[h] = 0.f; }

#pragma unroll
    for (int e4 = 0; e4 < EE / 4; e4++) {
        float4 xv = xr[e4];
        float xs[4] = {xv.x, xv.y, xv.z, xv.w};
#pragma unroll
        for (int j = 0; j < 4; j++) {
            int e = e4 * 4 + j;
#pragma unroll
            for (int h = 0; h < HS; h++) {
                q[h] = fmaf(xs[j], swq[e * HS + h], q[h]);
                k[h] = fmaf(xs[j], swk[e * HS + h], k[h]);
                v[h] = fmaf(xs[j], swv[e * HS + h], v[h]);
            }
        }
    }

    // RoPE (accurate sin/cos: phases reach ~2048 rad, fast-math would lose 1e-3)
    float qo[HS], ko[HS];
    float tf = (float)t;
#pragma unroll
    for (int i = 0; i < HS / 2; i++) {
        float inv = powf(10000.0f, -(float)i * (2.0f / (float)HS));
        float ang = tf * inv;
        float sn, cs;
        sincosf(ang, &sn, &cs);
        float qe = q[2 * i], qd = q[2 * i + 1];
        float ke = k[2 * i], kd = k[2 * i + 1];
        qo[2 * i]     = qe * cs - qd * sn;
        qo[2 * i + 1] = qe * sn + qd * cs;
        ko[2 * i]     = ke * cs - kd * sn;
        ko[2 * i + 1] = ke * sn + kd * cs;
    }

    float4* Q4 = reinterpret_cast<float4*>(g_q + (size_t)row * HS);
    float4* K4 = reinterpret_cast<float4*>(g_k + (size_t)row * HS);
    float4* V4 = reinterpret_cast<float4*>(g_v + (size_t)row * HS);
#pragma unroll
    for (int j = 0; j < 4; j++) {
        Q4[j] = make_float4(qo[4 * j], qo[4 * j + 1], qo[4 * j + 2], qo[4 * j + 3]);
        K4[j] = make_float4(ko[4 * j], ko[4 * j + 1], ko[4 * j + 2], ko[4 * j + 3]);
        V4[j] = make_float4(v[4 * j],  v[4 * j + 1],  v[4 * j + 2],  v[4 * j + 3]);
    }
}

// ---------------------------------------------------------------------------
// Kernel 2: causal flash attention, one thread per query row.
// Block = 128 threads = 128 consecutive query rows of one batch.
// K/V tiles (128 keys) staged in smem; scores computed in chunks of 16 so
// the online-softmax rescale is amortized 16x.
// ---------------------------------------------------------------------------
__global__ __launch_bounds__(128) void attn_kernel(float* __restrict__ out)
{
    int b  = blockIdx.x;
    int jt = (int)gridDim.y - 1 - (int)blockIdx.y;  // heavy tiles first
    int t  = jt * 128 + threadIdx.x;

    __shared__ float4 sk[KT * HS / 4];  // [KT][4 x float4]
    __shared__ float4 sv[KT * HS / 4];

    const float4* Qr = reinterpret_cast<const float4*>(g_q + ((size_t)b * TT + t) * HS);
    float q[HS];
#pragma unroll
    for (int j = 0; j < 4; j++) {
        float4 qv = Qr[j];
        q[4 * j] = qv.x; q[4 * j + 1] = qv.y; q[4 * j + 2] = qv.z; q[4 * j + 3] = qv.w;
    }

    const float4* Kb = reinterpret_cast<const float4*>(g_k + (size_t)b * TT * HS);
    const float4* Vb = reinterpret_cast<const float4*>(g_v + (size_t)b * TT * HS);

    float acc[HS];
#pragma unroll
    for (int h = 0; h < HS; h++) acc[h] = 0.f;
    float m = -1e30f, l = 0.f;

    int ntiles = jt + 1;
    for (int tile = 0; tile < ntiles; tile++) {
        int k0 = tile * KT;
        __syncthreads();
        {
            int r = threadIdx.x;   // one key row per thread
#pragma unroll
            for (int j = 0; j < 4; j++) {
                sk[r * 4 + j] = Kb[(size_t)(k0 + r) * 4 + j];
                sv[r * 4 + j] = Vb[(size_t)(k0 + r) * 4 + j];
            }
        }
        __syncthreads();

#pragma unroll 1
        for (int c0 = 0; c0 < KT; c0 += 16) {
            if (k0 + c0 > t) break;   // fully masked chunk -> done with this tile

            float s[16];
#pragma unroll
            for (int j = 0; j < 16; j++) {
                int key = c0 + j;
                float4 ka = sk[key * 4 + 0];
                float4 kb = sk[key * 4 + 1];
                float4 kc = sk[key * 4 + 2];
                float4 kd = sk[key * 4 + 3];
                float d0 = fmaf(q[0],  ka.x, fmaf(q[1],  ka.y, fmaf(q[2],  ka.z, q[3]  * ka.w)));
                float d1 = fmaf(q[4],  kb.x, fmaf(q[5],  kb.y, fmaf(q[6],  kb.z, q[7]  * kb.w)));
                float d2 = fmaf(q[8],  kc.x, fmaf(q[9],  kc.y, fmaf(q[10], kc.z, q[11] * kc.w)));
                float d3 = fmaf(q[12], kd.x, fmaf(q[13], kd.y, fmaf(q[14], kd.z, q[15] * kd.w)));
                float dot = (d0 + d1) + (d2 + d3);
                s[j] = (k0 + key <= t) ? dot * 0.25f : -1e30f;
            }

            float cm = s[0];
#pragma unroll
            for (int j = 1; j < 16; j++) cm = fmaxf(cm, s[j]);
            float mn = fmaxf(m, cm);
            float corr = __expf(m - mn);
            m = mn;
            l *= corr;
#pragma unroll
            for (int h = 0; h < HS; h++) acc[h] *= corr;

#pragma unroll
            for (int j = 0; j < 16; j++) {
                int key = c0 + j;
                float p = __expf(s[j] - mn);
                l += p;
                float4 va = sv[key * 4 + 0];
                float4 vb = sv[key * 4 + 1];
                float4 vc = sv[key * 4 + 2];
                float4 vd = sv[key * 4 + 3];
                acc[0]  = fmaf(p, va.x, acc[0]);
                acc[1]  = fmaf(p, va.y, acc[1]);
                acc[2]  = fmaf(p, va.z, acc[2]);
                acc[3]  = fmaf(p, va.w, acc[3]);
                acc[4]  = fmaf(p, vb.x, acc[4]);
                acc[5]  = fmaf(p, vb.y, acc[5]);
                acc[6]  = fmaf(p, vb.z, acc[6]);
                acc[7]  = fmaf(p, vb.w, acc[7]);
                acc[8]  = fmaf(p, vc.x, acc[8]);
                acc[9]  = fmaf(p, vc.y, acc[9]);
                acc[10] = fmaf(p, vc.z, acc[10]);
                acc[11] = fmaf(p, vc.w, acc[11]);
                acc[12] = fmaf(p, vd.x, acc[12]);
                acc[13] = fmaf(p, vd.y, acc[13]);
                acc[14] = fmaf(p, vd.z, acc[14]);
                acc[15] = fmaf(p, vd.w, acc[15]);
            }
        }
    }

    float inv_l = 1.0f / l;
    float4* Or = reinterpret_cast<float4*>(out + ((size_t)b * TT + t) * HS);
#pragma unroll
    for (int j = 0; j < 4; j++) {
        Or[j] = make_float4(acc[4 * j] * inv_l, acc[4 * j + 1] * inv_l,
                            acc[4 * j + 2] * inv_l, acc[4 * j + 3] * inv_l);
    }
}

extern "C" void kernel_launch(void* const* d_in, const int* in_sizes, int n_in,
                              void* d_out, int out_size)
{
    const float* x  = (const float*)d_in[0];
    const float* wq = (const float*)d_in[1];
    const float* wk = (const float*)d_in[2];
    const float* wv = (const float*)d_in[3];
    float* out = (float*)d_out;

    qkv_rope_kernel<<<(BB * TT) / 128, 128>>>(x, wq, wk, wv);

    dim3 grid(BB, TT / 128);
    attn_kernel<<<grid, 128>>>(out);
}

// round 3
// speedup vs baseline: 1.5966x; 1.5966x over previous
#include <cuda_runtime.h>
#include <math.h>

#define BB 16
#define TT 2048
#define EE 64
#define HS 16
#define KT 128            // keys per tile
#define NQT (TT / 128)    // 16 query tiles
#define NPAIR (NQT * (NQT + 1) / 2)   // 136 causal (jt,kt) pairs

// scratch: Q, K (post-RoPE) and V, [B*T, HS] row-major
__device__ float g_q[BB * TT * HS];
__device__ float g_k[BB * TT * HS];
__device__ float g_v[BB * TT * HS];
// partial results: [b][jt][kt][field][128], field: 0..15 acc, 16 m, 17 l
__device__ float g_part[BB * NQT * NQT * 18 * 128];

// ---------------------------------------------------------------------------
// Kernel 1: fused QKV projection + RoPE (one thread per (b,t) row)
// ---------------------------------------------------------------------------
__global__ __launch_bounds__(128) void qkv_rope_kernel(
    const float* __restrict__ x,
    const float* __restrict__ wq,
    const float* __restrict__ wk,
    const float* __restrict__ wv)
{
    __shared__ float swq[EE * HS];
    __shared__ float swk[EE * HS];
    __shared__ float swv[EE * HS];

    int tid = threadIdx.x;
    for (int i = tid; i < EE * HS; i += 128) {
        swq[i] = wq[i];
        swk[i] = wk[i];
        swv[i] = wv[i];
    }
    __syncthreads();

    int row = blockIdx.x * 128 + tid;
    int t = row & (TT - 1);

    const float4* xr = reinterpret_cast<const float4*>(x + (size_t)row * EE);

    float q[HS], k[HS], v[HS];
#pragma unroll
    for (int h = 0; h < HS; h++) { q[h] = 0.f; k[h] = 0.f; v[h] = 0.f; }

#pragma unroll
    for (int e4 = 0; e4 < EE / 4; e4++) {
        float4 xv = xr[e4];
        float xs[4] = {xv.x, xv.y, xv.z, xv.w};
#pragma unroll
        for (int j = 0; j < 4; j++) {
            int e = e4 * 4 + j;
#pragma unroll
            for (int h = 0; h < HS; h++) {
                q[h] = fmaf(xs[j], swq[e * HS + h], q[h]);
                k[h] = fmaf(xs[j], swk[e * HS + h], k[h]);
                v[h] = fmaf(xs[j], swv[e * HS + h], v[h]);
            }
        }
    }

    float qo[HS], ko[HS];
    float tf = (float)t;
#pragma unroll
    for (int i = 0; i < HS / 2; i++) {
        float inv = powf(10000.0f, -(float)i * (2.0f / (float)HS));
        float ang = tf * inv;
        float sn, cs;
        sincosf(ang, &sn, &cs);
        float qe = q[2 * i], qd = q[2 * i + 1];
        float ke = k[2 * i], kd = k[2 * i + 1];
        qo[2 * i]     = qe * cs - qd * sn;
        qo[2 * i + 1] = qe * sn + qd * cs;
        ko[2 * i]     = ke * cs - kd * sn;
        ko[2 * i + 1] = ke * sn + kd * cs;
    }

    float4* Q4 = reinterpret_cast<float4*>(g_q + (size_t)row * HS);
    float4* K4 = reinterpret_cast<float4*>(g_k + (size_t)row * HS);
    float4* V4 = reinterpret_cast<float4*>(g_v + (size_t)row * HS);
#pragma unroll
    for (int j = 0; j < 4; j++) {
        Q4[j] = make_float4(qo[4 * j], qo[4 * j + 1], qo[4 * j + 2], qo[4 * j + 3]);
        K4[j] = make_float4(ko[4 * j], ko[4 * j + 1], ko[4 * j + 2], ko[4 * j + 3]);
        V4[j] = make_float4(v[4 * j],  v[4 * j + 1],  v[4 * j + 2],  v[4 * j + 3]);
    }
}

// ---------------------------------------------------------------------------
// Kernel 2: partial flash attention on one 128q x 128k tile.
// One block per (b, jt, kt) causal pair; one thread per query row.
// ---------------------------------------------------------------------------
template <bool DIAG>
__device__ __forceinline__ void tile_body(
    const float4* __restrict__ sk,
    const float4* __restrict__ sv,
    const float* __restrict__ q,
    float* __restrict__ acc, float& m, float& l,
    int kmax)
{
#pragma unroll 1
    for (int c0 = 0; c0 < KT; c0 += 16) {
        if (DIAG) { if (c0 > kmax) break; }

        float s[16];
#pragma unroll
        for (int j = 0; j < 16; j++) {
            int key = c0 + j;
            float4 ka = sk[key * 4 + 0];
            float4 kb = sk[key * 4 + 1];
            float4 kc = sk[key * 4 + 2];
            float4 kd = sk[key * 4 + 3];
            float d0 = fmaf(q[0],  ka.x, fmaf(q[1],  ka.y, fmaf(q[2],  ka.z, q[3]  * ka.w)));
            float d1 = fmaf(q[4],  kb.x, fmaf(q[5],  kb.y, fmaf(q[6],  kb.z, q[7]  * kb.w)));
            float d2 = fmaf(q[8],  kc.x, fmaf(q[9],  kc.y, fmaf(q[10], kc.z, q[11] * kc.w)));
            float d3 = fmaf(q[12], kd.x, fmaf(q[13], kd.y, fmaf(q[14], kd.z, q[15] * kd.w)));
            float dot = (d0 + d1) + (d2 + d3);
            if (DIAG)
                s[j] = (key <= kmax) ? dot * 0.25f : -1e30f;
            else
                s[j] = dot * 0.25f;
        }

        float cm = s[0];
#pragma unroll
        for (int j = 1; j < 16; j++) cm = fmaxf(cm, s[j]);
        float mn = fmaxf(m, cm);
        float corr = __expf(m - mn);
        m = mn;
        l *= corr;
#pragma unroll
        for (int h = 0; h < HS; h++) acc[h] *= corr;

#pragma unroll
        for (int j = 0; j < 16; j++) {
            int key = c0 + j;
            float p = __expf(s[j] - mn);
            l += p;
            float4 va = sv[key * 4 + 0];
            float4 vb = sv[key * 4 + 1];
            float4 vc = sv[key * 4 + 2];
            float4 vd = sv[key * 4 + 3];
            acc[0]  = fmaf(p, va.x, acc[0]);
            acc[1]  = fmaf(p, va.y, acc[1]);
            acc[2]  = fmaf(p, va.z, acc[2]);
            acc[3]  = fmaf(p, va.w, acc[3]);
            acc[4]  = fmaf(p, vb.x, acc[4]);
            acc[5]  = fmaf(p, vb.y, acc[5]);
            acc[6]  = fmaf(p, vb.z, acc[6]);
            acc[7]  = fmaf(p, vb.w, acc[7]);
            acc[8]  = fmaf(p, vc.x, acc[8]);
            acc[9]  = fmaf(p, vc.y, acc[9]);
            acc[10] = fmaf(p, vc.z, acc[10]);
            acc[11] = fmaf(p, vc.w, acc[11]);
            acc[12] = fmaf(p, vd.x, acc[12]);
            acc[13] = fmaf(p, vd.y, acc[13]);
            acc[14] = fmaf(p, vd.z, acc[14]);
            acc[15] = fmaf(p, vd.w, acc[15]);
        }
    }
}

__global__ __launch_bounds__(128) void attn_part_kernel()
{
    int b = blockIdx.y;
    int p = blockIdx.x;

    // decode flat pair index -> (jt, kt), kt <= jt
    int jt = (int)((sqrtf(8.0f * (float)p + 1.0f) - 1.0f) * 0.5f);
    while ((jt + 1) * (jt + 2) / 2 <= p) jt++;
    while (jt * (jt + 1) / 2 > p) jt--;
    int kt = p - jt * (jt + 1) / 2;

    int tid = threadIdx.x;
    int t = jt * 128 + tid;
    int k0 = kt * KT;

    __shared__ float4 sk[KT * HS / 4];
    __shared__ float4 sv[KT * HS / 4];

    const float4* Kb = reinterpret_cast<const float4*>(g_k + (size_t)b * TT * HS);
    const float4* Vb = reinterpret_cast<const float4*>(g_v + (size_t)b * TT * HS);
    {
        int r = tid;
#pragma unroll
        for (int j = 0; j < 4; j++) {
            sk[r * 4 + j] = Kb[(size_t)(k0 + r) * 4 + j];
            sv[r * 4 + j] = Vb[(size_t)(k0 + r) * 4 + j];
        }
    }

    const float4* Qr = reinterpret_cast<const float4*>(g_q + ((size_t)b * TT + t) * HS);
    float q[HS];
#pragma unroll
    for (int j = 0; j < 4; j++) {
        float4 qv = Qr[j];
        q[4 * j] = qv.x; q[4 * j + 1] = qv.y; q[4 * j + 2] = qv.z; q[4 * j + 3] = qv.w;
    }

    float acc[HS];
#pragma unroll
    for (int h = 0; h < HS; h++) acc[h] = 0.f;
    float m = -1e30f, l = 0.f;

    __syncthreads();

    if (kt == jt)
        tile_body<true>(sk, sv, q, acc, m, l, tid);
    else
        tile_body<false>(sk, sv, q, acc, m, l, 127);

    // write partial: [b][jt][kt][field][128]
    float* dst = g_part + (((size_t)(b * NQT + jt) * NQT + kt) * 18) * 128 + tid;
#pragma unroll
    for (int h = 0; h < HS; h++) dst[h * 128] = acc[h];
    dst[16 * 128] = m;
    dst[17 * 128] = l;
}

// ---------------------------------------------------------------------------
// Kernel 3: combine partials across key tiles for each query row.
// ---------------------------------------------------------------------------
__global__ __launch_bounds__(128) void combine_kernel(float* __restrict__ out)
{
    int jt = blockIdx.x;
    int b  = blockIdx.y;
    int tid = threadIdx.x;
    int n = jt + 1;

    const float* base = g_part + ((size_t)(b * NQT + jt) * NQT * 18) * 128 + tid;

    float m_tot = -1e30f;
#pragma unroll 1
    for (int i = 0; i < n; i++)
        m_tot = fmaxf(m_tot, base[(size_t)i * 18 * 128 + 16 * 128]);

    float acc[HS];
#pragma unroll
    for (int h = 0; h < HS; h++) acc[h] = 0.f;
    float l_tot = 0.f;

#pragma unroll 1
    for (int i = 0; i < n; i++) {
        const float* pp = base + (size_t)i * 18 * 128;
        float w = __expf(pp[16 * 128] - m_tot);
        l_tot = fmaf(pp[17 * 128], w, l_tot);
#pragma unroll
        for (int h = 0; h < HS; h++) acc[h] = fmaf(pp[h * 128], w, acc[h]);
    }

    float inv_l = 1.0f / l_tot;
    int t = jt * 128 + tid;
    float4* Or = reinterpret_cast<float4*>(out + ((size_t)b * TT + t) * HS);
#pragma unroll
    for (int j = 0; j < 4; j++)
        Or[j] = make_float4(acc[4 * j] * inv_l, acc[4 * j + 1] * inv_l,
                            acc[4 * j + 2] * inv_l, acc[4 * j + 3] * inv_l);
}

extern "C" void kernel_launch(void* const* d_in, const int* in_sizes, int n_in,
                              void* d_out, int out_size)
{
    const float* x  = (const float*)d_in[0];
    const float* wq = (const float*)d_in[1];
    const float* wk = (const float*)d_in[2];
    const float* wv = (const float*)d_in[3];
    float* out = (float*)d_out;

    qkv_rope_kernel<<<(BB * TT) / 128, 128>>>(x, wq, wk, wv);

    dim3 grid_p(NPAIR, BB);
    attn_part_kernel<<<grid_p, 128>>>();

    dim3 grid_c(NQT, BB);
    combine_kernel<<<grid_c, 128>>>(out);
}

// round 4
// speedup vs baseline: 1.6508x; 1.0339x over previous
#include <cuda_runtime.h>
#include <math.h>

#define BB 16
#define TT 2048
#define EE 64
#define HS 16
#define KT 128            // keys per tile
#define NQT (TT / 128)    // 16 query tiles
#define NPAIR (NQT * (NQT + 1) / 2)   // 136 causal (jt,kt) pairs

typedef unsigned long long u64;

// ---- packed f32x2 helpers (sm_100+; ptxas will not auto-fuse, must be PTX) ----
__device__ __forceinline__ u64 ffma2(u64 a, u64 b, u64 c) {
    u64 d; asm("fma.rn.f32x2 %0,%1,%2,%3;" : "=l"(d) : "l"(a), "l"(b), "l"(c)); return d;
}
__device__ __forceinline__ u64 fmul2(u64 a, u64 b) {
    u64 d; asm("mul.rn.f32x2 %0,%1,%2;" : "=l"(d) : "l"(a), "l"(b)); return d;
}
__device__ __forceinline__ u64 fadd2(u64 a, u64 b) {
    u64 d; asm("add.rn.f32x2 %0,%1,%2;" : "=l"(d) : "l"(a), "l"(b)); return d;
}
__device__ __forceinline__ u64 pack2(float x, float y) {
    u64 d; asm("mov.b64 %0,{%1,%2};" : "=l"(d) : "f"(x), "f"(y)); return d;
}
__device__ __forceinline__ float2 unpack2(u64 a) {
    float x, y; asm("mov.b64 {%0,%1},%2;" : "=f"(x), "=f"(y) : "l"(a)); return make_float2(x, y);
}
__device__ __forceinline__ float ex2f(float x) {
    float y; asm("ex2.approx.f32 %0,%1;" : "=f"(y) : "f"(x)); return y;
}

// scratch
__device__ float g_q[BB * TT * HS];
__device__ float g_k[BB * TT * HS];
__device__ float g_v[BB * TT * HS];
__device__ float g_rope[TT * HS];   // [t][2i]=cos, [t][2i+1]=sin
// partials: [b][jt][kt][field][128], field: 0..15 acc, 16 m, 17 l  (m in log2 domain)
__device__ float g_part[BB * NQT * NQT * 18 * 128];

// log2(e) * hs^-0.5
#define QSCALE 0.360673760222241f

// ---------------------------------------------------------------------------
// Kernel 0: RoPE cos/sin table. One thread per (t, i).
// ---------------------------------------------------------------------------
__global__ __launch_bounds__(128) void rope_table_kernel()
{
    int idx = blockIdx.x * 128 + threadIdx.x;   // 0 .. TT*8-1
    int t = idx >> 3;
    int i = idx & 7;
    float inv = powf(10000.0f, -(float)i * (2.0f / (float)HS));
    float sn, cs;
    sincosf((float)t * inv, &sn, &cs);
    g_rope[t * 16 + 2 * i]     = cs;
    g_rope[t * 16 + 2 * i + 1] = sn;
}

// ---------------------------------------------------------------------------
// Kernel 1: fused QKV projection + RoPE (one thread per (b,t) row)
// ---------------------------------------------------------------------------
__global__ __launch_bounds__(128) void qkv_rope_kernel(
    const float* __restrict__ x,
    const float* __restrict__ wq,
    const float* __restrict__ wk,
    const float* __restrict__ wv)
{
    __shared__ float swq[EE * HS];
    __shared__ float swk[EE * HS];
    __shared__ float swv[EE * HS];

    int tid = threadIdx.x;
    for (int i = tid; i < EE * HS; i += 128) {
        swq[i] = wq[i];
        swk[i] = wk[i];
        swv[i] = wv[i];
    }
    __syncthreads();

    int row = blockIdx.x * 128 + tid;
    int t = row & (TT - 1);

    const float4* xr = reinterpret_cast<const float4*>(x + (size_t)row * EE);

    float q[HS], k[HS], v[HS];
#pragma unroll
    for (int h = 0; h < HS; h++) { q[h] = 0.f; k[h] = 0.f; v[h] = 0.f; }

#pragma unroll
    for (int e4 = 0; e4 < EE / 4; e4++) {
        float4 xv = xr[e4];
        float xs[4] = {xv.x, xv.y, xv.z, xv.w};
#pragma unroll
        for (int j = 0; j < 4; j++) {
            int e = e4 * 4 + j;
#pragma unroll
            for (int h = 0; h < HS; h++) {
                q[h] = fmaf(xs[j], swq[e * HS + h], q[h]);
                k[h] = fmaf(xs[j], swk[e * HS + h], k[h]);
                v[h] = fmaf(xs[j], swv[e * HS + h], v[h]);
            }
        }
    }

    // RoPE from precomputed table
    const float4* rp = reinterpret_cast<const float4*>(g_rope + t * 16);
    float rope[16];
#pragma unroll
    for (int j = 0; j < 4; j++) {
        float4 rv = rp[j];
        rope[4 * j] = rv.x; rope[4 * j + 1] = rv.y;
        rope[4 * j + 2] = rv.z; rope[4 * j + 3] = rv.w;
    }

    float qo[HS], ko[HS];
#pragma unroll
    for (int i = 0; i < HS / 2; i++) {
        float cs = rope[2 * i], sn = rope[2 * i + 1];
        float qe = q[2 * i], qd = q[2 * i + 1];
        float ke = k[2 * i], kd = k[2 * i + 1];
        qo[2 * i]     = qe * cs - qd * sn;
        qo[2 * i + 1] = qe * sn + qd * cs;
        ko[2 * i]     = ke * cs - kd * sn;
        ko[2 * i + 1] = ke * sn + kd * cs;
    }

    float4* Q4 = reinterpret_cast<float4*>(g_q + (size_t)row * HS);
    float4* K4 = reinterpret_cast<float4*>(g_k + (size_t)row * HS);
    float4* V4 = reinterpret_cast<float4*>(g_v + (size_t)row * HS);
#pragma unroll
    for (int j = 0; j < 4; j++) {
        Q4[j] = make_float4(qo[4 * j], qo[4 * j + 1], qo[4 * j + 2], qo[4 * j + 3]);
        K4[j] = make_float4(ko[4 * j], ko[4 * j + 1], ko[4 * j + 2], ko[4 * j + 3]);
        V4[j] = make_float4(v[4 * j],  v[4 * j + 1],  v[4 * j + 2],  v[4 * j + 3]);
    }
}

// ---------------------------------------------------------------------------
// Kernel 2: partial flash attention on one 128q x 128k tile, f32x2-packed.
// Scores and m are kept in the log2 domain (q pre-scaled by QSCALE).
// ---------------------------------------------------------------------------
template <bool DIAG>
__device__ __forceinline__ void tile_body(
    const ulonglong2* __restrict__ sk,
    const ulonglong2* __restrict__ sv,
    const u64* __restrict__ qp,
    u64* __restrict__ acc, float& m, float& l,
    int kmax)
{
#pragma unroll 1
    for (int c0 = 0; c0 < KT; c0 += 16) {
        if (DIAG) { if (c0 > kmax) break; }

        float s[16];
#pragma unroll
        for (int j = 0; j < 16; j++) {
            int key = c0 + j;
            ulonglong2 ka = sk[key * 4 + 0];
            ulonglong2 kb = sk[key * 4 + 1];
            ulonglong2 kc = sk[key * 4 + 2];
            ulonglong2 kd = sk[key * 4 + 3];
            u64 d0 = fmul2(qp[0], ka.x);
            d0 = ffma2(qp[1], ka.y, d0);
            d0 = ffma2(qp[2], kb.x, d0);
            d0 = ffma2(qp[3], kb.y, d0);
            u64 d1 = fmul2(qp[4], kc.x);
            d1 = ffma2(qp[5], kc.y, d1);
            d1 = ffma2(qp[6], kd.x, d1);
            d1 = ffma2(qp[7], kd.y, d1);
            float2 f = unpack2(fadd2(d0, d1));
            float dot = f.x + f.y;
            if (DIAG)
                s[j] = (key <= kmax) ? dot : -1e30f;
            else
                s[j] = dot;
        }

        float cm = s[0];
#pragma unroll
        for (int j = 1; j < 16; j++) cm = fmaxf(cm, s[j]);
        float mn = fmaxf(m, cm);
        float corr = ex2f(m - mn);
        m = mn;
        l *= corr;
        u64 c2 = pack2(corr, corr);
#pragma unroll
        for (int h = 0; h < 8; h++) acc[h] = fmul2(acc[h], c2);

#pragma unroll
        for (int j = 0; j < 16; j++) {
            int key = c0 + j;
            float p = ex2f(s[j] - mn);
            l += p;
            u64 p2 = pack2(p, p);
            ulonglong2 va = sv[key * 4 + 0];
            ulonglong2 vb = sv[key * 4 + 1];
            ulonglong2 vc = sv[key * 4 + 2];
            ulonglong2 vd = sv[key * 4 + 3];
            acc[0] = ffma2(p2, va.x, acc[0]);
            acc[1] = ffma2(p2, va.y, acc[1]);
            acc[2] = ffma2(p2, vb.x, acc[2]);
            acc[3] = ffma2(p2, vb.y, acc[3]);
            acc[4] = ffma2(p2, vc.x, acc[4]);
            acc[5] = ffma2(p2, vc.y, acc[5]);
            acc[6] = ffma2(p2, vd.x, acc[6]);
            acc[7] = ffma2(p2, vd.y, acc[7]);
        }
    }
}

__global__ __launch_bounds__(128) void attn_part_kernel()
{
    int b = blockIdx.y;
    int p = blockIdx.x;

    // decode flat pair index -> (jt, kt), kt <= jt
    int jt = (int)((sqrtf(8.0f * (float)p + 1.0f) - 1.0f) * 0.5f);
    while ((jt + 1) * (jt + 2) / 2 <= p) jt++;
    while (jt * (jt + 1) / 2 > p) jt--;
    int kt = p - jt * (jt + 1) / 2;

    int tid = threadIdx.x;
    int t = jt * 128 + tid;
    int k0 = kt * KT;

    __shared__ ulonglong2 sk[KT * 4];
    __shared__ ulonglong2 sv[KT * 4];

    const ulonglong2* Kb = reinterpret_cast<const ulonglong2*>(g_k + (size_t)b * TT * HS);
    const ulonglong2* Vb = reinterpret_cast<const ulonglong2*>(g_v + (size_t)b * TT * HS);
    {
        int r = tid;
#pragma unroll
        for (int j = 0; j < 4; j++) {
            sk[r * 4 + j] = Kb[(size_t)(k0 + r) * 4 + j];
            sv[r * 4 + j] = Vb[(size_t)(k0 + r) * 4 + j];
        }
    }

    const float4* Qr = reinterpret_cast<const float4*>(g_q + ((size_t)b * TT + t) * HS);
    u64 qp[8];
#pragma unroll
    for (int j = 0; j < 4; j++) {
        float4 qv = Qr[j];
        qp[2 * j]     = pack2(qv.x * QSCALE, qv.y * QSCALE);
        qp[2 * j + 1] = pack2(qv.z * QSCALE, qv.w * QSCALE);
    }

    u64 acc[8];
    u64 zz = pack2(0.f, 0.f);
#pragma unroll
    for (int h = 0; h < 8; h++) acc[h] = zz;
    float m = -1e30f, l = 0.f;

    __syncthreads();

    if (kt == jt)
        tile_body<true>(sk, sv, qp, acc, m, l, tid);
    else
        tile_body<false>(sk, sv, qp, acc, m, l, 127);

    // write partial: [b][jt][kt][field][128]
    float* dst = g_part + (((size_t)(b * NQT + jt) * NQT + kt) * 18) * 128 + tid;
#pragma unroll
    for (int h = 0; h < 8; h++) {
        float2 f = unpack2(acc[h]);
        dst[(2 * h) * 128]     = f.x;
        dst[(2 * h + 1) * 128] = f.y;
    }
    dst[16 * 128] = m;
    dst[17 * 128] = l;
}

// ---------------------------------------------------------------------------
// Kernel 3: combine partials across key tiles (m is in log2 domain).
// ---------------------------------------------------------------------------
__global__ __launch_bounds__(128) void combine_kernel(float* __restrict__ out)
{
    int jt = blockIdx.x;
    int b  = blockIdx.y;
    int tid = threadIdx.x;
    int n = jt + 1;

    const float* base = g_part + ((size_t)(b * NQT + jt) * NQT * 18) * 128 + tid;

    float m_tot = -1e30f;
#pragma unroll 1
    for (int i = 0; i < n; i++)
        m_tot = fmaxf(m_tot, base[(size_t)i * 18 * 128 + 16 * 128]);

    float acc[HS];
#pragma unroll
    for (int h = 0; h < HS; h++) acc[h] = 0.f;
    float l_tot = 0.f;

#pragma unroll 1
    for (int i = 0; i < n; i++) {
        const float* pp = base + (size_t)i * 18 * 128;
        float w = ex2f(pp[16 * 128] - m_tot);
        l_tot = fmaf(pp[17 * 128], w, l_tot);
#pragma unroll
        for (int h = 0; h < HS; h++) acc[h] = fmaf(pp[h * 128], w, acc[h]);
    }

    float inv_l = 1.0f / l_tot;
    int t = jt * 128 + tid;
    float4* Or = reinterpret_cast<float4*>(out + ((size_t)b * TT + t) * HS);
#pragma unroll
    for (int j = 0; j < 4; j++)
        Or[j] = make_float4(acc[4 * j] * inv_l, acc[4 * j + 1] * inv_l,
                            acc[4 * j + 2] * inv_l, acc[4 * j + 3] * inv_l);
}

extern "C" void kernel_launch(void* const* d_in, const int* in_sizes, int n_in,
                              void* d_out, int out_size)
{
    const float* x  = (const float*)d_in[0];
    const float* wq = (const float*)d_in[1];
    const float* wk = (const float*)d_in[2];
    const float* wv = (const float*)d_in[3];
    float* out = (float*)d_out;

    rope_table_kernel<<<(TT * 8) / 128, 128>>>();
    qkv_rope_kernel<<<(BB * TT) / 128, 128>>>(x, wq, wk, wv);

    dim3 grid_p(NPAIR, BB);
    attn_part_kernel<<<grid_p, 128>>>();

    dim3 grid_c(NQT, BB);
    combine_kernel<<<grid_c, 128>>>(out);
}

// round 6
// speedup vs baseline: 1.7445x; 1.0567x over previous
#include <cuda_runtime.h>
#include <math.h>

#define BB 16
#define TT 2048
#define EE 64
#define HS 16
#define NQT (TT / 128)    // 16 query tiles
#define NKP 8             // max k-pairs (256-key supertiles) per query tile
#define NPAIR2 72         // sum_{jt=0..15} ceil((jt+1)/2)

typedef unsigned long long u64;

// ---- packed f32x2 helpers (sm_100+) ----
__device__ __forceinline__ u64 ffma2(u64 a, u64 b, u64 c) {
    u64 d; asm("fma.rn.f32x2 %0,%1,%2,%3;" : "=l"(d) : "l"(a), "l"(b), "l"(c)); return d;
}
__device__ __forceinline__ u64 fmul2(u64 a, u64 b) {
    u64 d; asm("mul.rn.f32x2 %0,%1,%2;" : "=l"(d) : "l"(a), "l"(b)); return d;
}
__device__ __forceinline__ u64 fadd2(u64 a, u64 b) {
    u64 d; asm("add.rn.f32x2 %0,%1,%2;" : "=l"(d) : "l"(a), "l"(b)); return d;
}
__device__ __forceinline__ u64 pack2(float x, float y) {
    u64 d; asm("mov.b64 %0,{%1,%2};" : "=l"(d) : "f"(x), "f"(y)); return d;
}
__device__ __forceinline__ float2 unpack2(u64 a) {
    float x, y; asm("mov.b64 {%0,%1},%2;" : "=f"(x), "=f"(y) : "l"(a)); return make_float2(x, y);
}
__device__ __forceinline__ float ex2f(float x) {
    float y; asm("ex2.approx.f32 %0,%1;" : "=f"(y) : "f"(x)); return y;
}

// scratch
__device__ float g_q[BB * TT * HS];
__device__ float g_k[BB * TT * HS];
__device__ float g_v[BB * TT * HS];
__device__ float g_rope[TT * HS];   // [t][2i]=cos, [t][2i+1]=sin
// partials (per 256-key supertile): acc as 4 coalesced float4 fields, (m,l) as float2
__device__ float4 g_part4[BB * NQT * NKP * 4 * 128];
__device__ float2 g_ml[BB * NQT * NKP * 128];

// log2(e) * hs^-0.5
#define QSCALE 0.360673760222241f

// ---------------------------------------------------------------------------
// Kernel 0: RoPE cos/sin table. One thread per (t, i).
// ---------------------------------------------------------------------------
__global__ __launch_bounds__(128) void rope_table_kernel()
{
    int idx = blockIdx.x * 128 + threadIdx.x;   // 0 .. TT*8-1
    int t = idx >> 3;
    int i = idx & 7;
    float inv = powf(10000.0f, -(float)i * (2.0f / (float)HS));
    float sn, cs;
    sincosf((float)t * inv, &sn, &cs);
    g_rope[t * 16 + 2 * i]     = cs;
    g_rope[t * 16 + 2 * i + 1] = sn;
}

// ---------------------------------------------------------------------------
// Kernel 1: fused QKV projection + RoPE (one thread per (b,t) row)
// ---------------------------------------------------------------------------
__global__ __launch_bounds__(128) void qkv_rope_kernel(
    const float* __restrict__ x,
    const float* __restrict__ wq,
    const float* __restrict__ wk,
    const float* __restrict__ wv)
{
    __shared__ float swq[EE * HS];
    __shared__ float swk[EE * HS];
    __shared__ float swv[EE * HS];

    int tid = threadIdx.x;
    for (int i = tid; i < EE * HS; i += 128) {
        swq[i] = wq[i];
        swk[i] = wk[i];
        swv[i] = wv[i];
    }
    __syncthreads();

    int row = blockIdx.x * 128 + tid;
    int t = row & (TT - 1);

    const float4* xr = reinterpret_cast<const float4*>(x + (size_t)row * EE);

    float q[HS], k[HS], v[HS];
#pragma unroll
    for (int h = 0; h < HS; h++) { q[h] = 0.f; k[h] = 0.f; v[h] = 0.f; }

#pragma unroll
    for (int e4 = 0; e4 < EE / 4; e4++) {
        float4 xv = xr[e4];
        float xs[4] = {xv.x, xv.y, xv.z, xv.w};
#pragma unroll
        for (int j = 0; j < 4; j++) {
            int e = e4 * 4 + j;
#pragma unroll
            for (int h = 0; h < HS; h++) {
                q[h] = fmaf(xs[j], swq[e * HS + h], q[h]);
                k[h] = fmaf(xs[j], swk[e * HS + h], k[h]);
                v[h] = fmaf(xs[j], swv[e * HS + h], v[h]);
            }
        }
    }

    const float4* rp = reinterpret_cast<const float4*>(g_rope + t * 16);
    float rope[16];
#pragma unroll
    for (int j = 0; j < 4; j++) {
        float4 rv = rp[j];
        rope[4 * j] = rv.x; rope[4 * j + 1] = rv.y;
        rope[4 * j + 2] = rv.z; rope[4 * j + 3] = rv.w;
    }

    float qo[HS], ko[HS];
#pragma unroll
    for (int i = 0; i < HS / 2; i++) {
        float cs = rope[2 * i], sn = rope[2 * i + 1];
        float qe = q[2 * i], qd = q[2 * i + 1];
        float ke = k[2 * i], kd = k[2 * i + 1];
        qo[2 * i]     = qe * cs - qd * sn;
        qo[2 * i + 1] = qe * sn + qd * cs;
        ko[2 * i]     = ke * cs - kd * sn;
        ko[2 * i + 1] = ke * sn + kd * cs;
    }

    float4* Q4 = reinterpret_cast<float4*>(g_q + (size_t)row * HS);
    float4* K4 = reinterpret_cast<float4*>(g_k + (size_t)row * HS);
    float4* V4 = reinterpret_cast<float4*>(g_v + (size_t)row * HS);
#pragma unroll
    for (int j = 0; j < 4; j++) {
        Q4[j] = make_float4(qo[4 * j], qo[4 * j + 1], qo[4 * j + 2], qo[4 * j + 3]);
        K4[j] = make_float4(ko[4 * j], ko[4 * j + 1], ko[4 * j + 2], ko[4 * j + 3]);
        V4[j] = make_float4(v[4 * j],  v[4 * j + 1],  v[4 * j + 2],  v[4 * j + 3]);
    }
}

// ---------------------------------------------------------------------------
// Kernel 2: partial flash attention, one block per (b, jt, 256-key supertile).
// ---------------------------------------------------------------------------
template <bool DIAG>
__device__ __forceinline__ void tile_body(
    const ulonglong2* __restrict__ sk,
    const ulonglong2* __restrict__ sv,
    const u64* __restrict__ qp,
    u64* __restrict__ acc, float& m, float& l,
    int kmax)
{
#pragma unroll 1
    for (int c0 = 0; c0 < 128; c0 += 16) {
        if (DIAG) { if (c0 > kmax) break; }

        float s[16];
#pragma unroll
        for (int j = 0; j < 16; j++) {
            int key = c0 + j;
            ulonglong2 ka = sk[key * 4 + 0];
            ulonglong2 kb = sk[key * 4 + 1];
            ulonglong2 kc = sk[key * 4 + 2];
            ulonglong2 kd = sk[key * 4 + 3];
            u64 d0 = fmul2(qp[0], ka.x);
            d0 = ffma2(qp[1], ka.y, d0);
            d0 = ffma2(qp[2], kb.x, d0);
            d0 = ffma2(qp[3], kb.y, d0);
            u64 d1 = fmul2(qp[4], kc.x);
            d1 = ffma2(qp[5], kc.y, d1);
            d1 = ffma2(qp[6], kd.x, d1);
            d1 = ffma2(qp[7], kd.y, d1);
            float2 f = unpack2(fadd2(d0, d1));
            float dot = f.x + f.y;
            if (DIAG)
                s[j] = (key <= kmax) ? dot : -1e30f;
            else
                s[j] = dot;
        }

        float cm = s[0];
#pragma unroll
        for (int j = 1; j < 16; j++) cm = fmaxf(cm, s[j]);
        float mn = fmaxf(m, cm);
        float corr = ex2f(m - mn);
        m = mn;
        l *= corr;
        u64 c2 = pack2(corr, corr);
#pragma unroll
        for (int h = 0; h < 8; h++) acc[h] = fmul2(acc[h], c2);

#pragma unroll
        for (int j = 0; j < 16; j++) {
            int key = c0 + j;
            float p = ex2f(s[j] - mn);
            l += p;
            u64 p2 = pack2(p, p);
            ulonglong2 va = sv[key * 4 + 0];
            ulonglong2 vb = sv[key * 4 + 1];
            ulonglong2 vc = sv[key * 4 + 2];
            ulonglong2 vd = sv[key * 4 + 3];
            acc[0] = ffma2(p2, va.x, acc[0]);
            acc[1] = ffma2(p2, va.y, acc[1]);
            acc[2] = ffma2(p2, vb.x, acc[2]);
            acc[3] = ffma2(p2, vb.y, acc[3]);
            acc[4] = ffma2(p2, vc.x, acc[4]);
            acc[5] = ffma2(p2, vc.y, acc[5]);
            acc[6] = ffma2(p2, vd.x, acc[6]);
            acc[7] = ffma2(p2, vd.y, acc[7]);
        }
    }
}

__global__ __launch_bounds__(128) void attn_part_kernel()
{
    int b = blockIdx.y;
    int p = blockIdx.x;

    // decode flat index -> (jt, kp): kp-th 256-key supertile of query tile jt
    int jt = 0, rem = p;
    while (rem >= (jt + 2) / 2) { rem -= (jt + 2) / 2; jt++; }
    int kp = rem;

    int tid = threadIdx.x;
    int t = jt * 128 + tid;
    int kt0 = 2 * kp;
    int k0 = kt0 * 128;

    __shared__ ulonglong2 sk[256 * 4];   // 256 keys
    __shared__ ulonglong2 sv[256 * 4];

    const ulonglong2* Kb = reinterpret_cast<const ulonglong2*>(g_k + (size_t)b * TT * HS);
    const ulonglong2* Vb = reinterpret_cast<const ulonglong2*>(g_v + (size_t)b * TT * HS);
#pragma unroll
    for (int rr = 0; rr < 2; rr++) {
        int r = tid + rr * 128;
#pragma unroll
        for (int j = 0; j < 4; j++) {
            sk[r * 4 + j] = Kb[(size_t)(k0 + r) * 4 + j];
            sv[r * 4 + j] = Vb[(size_t)(k0 + r) * 4 + j];
        }
    }

    const float4* Qr = reinterpret_cast<const float4*>(g_q + ((size_t)b * TT + t) * HS);
    u64 qp[8];
#pragma unroll
    for (int j = 0; j < 4; j++) {
        float4 qv = Qr[j];
        qp[2 * j]     = pack2(qv.x * QSCALE, qv.y * QSCALE);
        qp[2 * j + 1] = pack2(qv.z * QSCALE, qv.w * QSCALE);
    }

    u64 acc[8];
    u64 zz = pack2(0.f, 0.f);
#pragma unroll
    for (int h = 0; h < 8; h++) acc[h] = zz;
    float m = -1e30f, l = 0.f;

    __syncthreads();

    // tile 0 of the supertile
    if (kt0 == jt)
        tile_body<true>(sk, sv, qp, acc, m, l, tid);
    else
        tile_body<false>(sk, sv, qp, acc, m, l, 127);

    // tile 1 (if in causal range)
    if (kt0 + 1 <= jt) {
        if (kt0 + 1 == jt)
            tile_body<true>(sk + 512, sv + 512, qp, acc, m, l, tid);
        else
            tile_body<false>(sk + 512, sv + 512, qp, acc, m, l, 127);
    }

    // write partial
    size_t pb = ((size_t)(b * NQT + jt) * NKP + kp);
    float4* dst = g_part4 + pb * 4 * 128 + tid;
#pragma unroll
    for (int h = 0; h < 4; h++) {
        float2 f0 = unpack2(acc[2 * h]);
        float2 f1 = unpack2(acc[2 * h + 1]);
        dst[h * 128] = make_float4(f0.x, f0.y, f1.x, f1.y);
    }
    g_ml[pb * 128 + tid] = make_float2(m, l);
}

// ---------------------------------------------------------------------------
// Kernel 3: combine partials (m in log2 domain). n <= 8 supertiles.
// ---------------------------------------------------------------------------
__global__ __launch_bounds__(128) void combine_kernel(float* __restrict__ out)
{
    int jt = blockIdx.x;
    int b  = blockIdx.y;
    int tid = threadIdx.x;
    int n = (jt + 2) / 2;

    const float4* base = g_part4 + (size_t)(b * NQT + jt) * NKP * 4 * 128 + tid;
    const float2* mlb  = g_ml    + (size_t)(b * NQT + jt) * NKP * 128 + tid;

    // all (m,l) in flight at once
    float2 ml[NKP];
#pragma unroll
    for (int i = 0; i < NKP; i++)
        ml[i] = (i < n) ? mlb[i * 128] : make_float2(-1e30f, 0.f);

    float m_tot = ml[0].x;
#pragma unroll
    for (int i = 1; i < NKP; i++) m_tot = fmaxf(m_tot, ml[i].x);

    float acc[HS];
#pragma unroll
    for (int h = 0; h < HS; h++) acc[h] = 0.f;
    float l_tot = 0.f;

#pragma unroll 2
    for (int i = 0; i < n; i++) {
        const float4* pp = base + (size_t)i * 4 * 128;
        float4 a0 = pp[0];
        float4 a1 = pp[128];
        float4 a2 = pp[256];
        float4 a3 = pp[384];
        float w = ex2f(ml[i].x - m_tot);
        l_tot = fmaf(ml[i].y, w, l_tot);
        acc[0]  = fmaf(a0.x, w, acc[0]);
        acc[1]  = fmaf(a0.y, w, acc[1]);
        acc[2]  = fmaf(a0.z, w, acc[2]);
        acc[3]  = fmaf(a0.w, w, acc[3]);
        acc[4]  = fmaf(a1.x, w, acc[4]);
        acc[5]  = fmaf(a1.y, w, acc[5]);
        acc[6]  = fmaf(a1.z, w, acc[6]);
        acc[7]  = fmaf(a1.w, w, acc[7]);
        acc[8]  = fmaf(a2.x, w, acc[8]);
        acc[9]  = fmaf(a2.y, w, acc[9]);
        acc[10] = fmaf(a2.z, w, acc[10]);
        acc[11] = fmaf(a2.w, w, acc[11]);
        acc[12] = fmaf(a3.x, w, acc[12]);
        acc[13] = fmaf(a3.y, w, acc[13]);
        acc[14] = fmaf(a3.z, w, acc[14]);
        acc[15] = fmaf(a3.w, w, acc[15]);
    }

    float inv_l = 1.0f / l_tot;
    int t = jt * 128 + tid;
    float4* Or = reinterpret_cast<float4*>(out + ((size_t)b * TT + t) * HS);
#pragma unroll
    for (int j = 0; j < 4; j++)
        Or[j] = make_float4(acc[4 * j] * inv_l, acc[4 * j + 1] * inv_l,
                            acc[4 * j + 2] * inv_l, acc[4 * j + 3] * inv_l);
}

extern "C" void kernel_launch(void* const* d_in, const int* in_sizes, int n_in,
                              void* d_out, int out_size)
{
    const float* x  = (const float*)d_in[0];
    const float* wq = (const float*)d_in[1];
    const float* wk = (const float*)d_in[2];
    const float* wv = (const float*)d_in[3];
    float* out = (float*)d_out;

    rope_table_kernel<<<(TT * 8) / 128, 128>>>();
    qkv_rope_kernel<<<(BB * TT) / 128, 128>>>(x, wq, wk, wv);

    dim3 grid_p(NPAIR2, BB);
    attn_part_kernel<<<grid_p, 128>>>();

    dim3 grid_c(NQT, BB);
    combine_kernel<<<grid_c, 128>>>(out);
}